// round 4
// baseline (speedup 1.0000x reference)
#include <cuda_runtime.h>
#include <cuda_bf16.h>
#include <cstdint>

// ---------------- problem constants ----------------
#define NN 32768
#define DD 160     // = 10 k-steps of 16
#define FF 128
#define HH 32      // = 4 n-tiles of 8 = 2 k-steps of 16
#define KS1 10     // layer-1 k-steps
#define ROWS 128   // rows per CTA (8 warps x 1 m-tile)
#define NF 16      // networks per CTA
#define NTHR 256

#define GMT (NN / 16)              // 2048 global m-tiles
#define WBLK 25088                 // per-f weight block bytes
#define NSLOT 4                    // W ring depth

// ---------------- device scratch (no allocs) ----------------
__device__ __align__(16) uint4 g_XfragH[(size_t)GMT * KS1 * 32];   // 10.5 MB
__device__ __align__(16) uint4 g_XfragL[(size_t)GMT * KS1 * 32];   // 10.5 MB
__device__ __align__(16) unsigned char g_Wblk[(size_t)FF * WBLK];  // 3.2 MB
// per-f block: W1H[1280]u2 @0 | W1L @10240 | W2H[256]u2 @20480 | W2L @22528 | misc 128 floats @24576

// ---------------- helpers ----------------
__device__ __forceinline__ uint32_t smem_u32(const void* p) {
    uint32_t a;
    asm("{ .reg .u64 t; cvta.to.shared.u64 t, %1; cvt.u32.u64 %0, t; }" : "=r"(a) : "l"(p));
    return a;
}
#define MBARRIER_INIT(addr, cnt) \
    asm volatile("mbarrier.init.shared.b64 [%0], %1;" :: "r"((uint32_t)(addr)), "r"((uint32_t)(cnt)) : "memory")
#define MBARRIER_EXPECT_TX(addr, bytes) \
    asm volatile("mbarrier.arrive.expect_tx.shared.b64 _, [%0], %1;" :: "r"((uint32_t)(addr)), "r"((uint32_t)(bytes)) : "memory")
#define MBARRIER_WAIT_PARITY(mbar_smem_addr, phase_parity) do { \
    uint32_t _mbar = (uint32_t)(mbar_smem_addr); \
    uint32_t _parity = (uint32_t)(phase_parity); \
    uint32_t _done; \
    asm volatile("{\n\t.reg .pred p;\n\t" \
        "mbarrier.try_wait.parity.acquire.cta.shared::cta.b64 p, [%1], %2;\n\t" \
        "selp.b32 %0, 1, 0, p;\n\t}" : "=r"(_done) : "r"(_mbar), "r"(_parity) : "memory"); \
    if (!_done) { \
        asm volatile("{\n\t.reg .pred P1;\n\t" \
            "WAIT_LOOP_%=:\n\t" \
            "mbarrier.try_wait.parity.acquire.cta.shared::cta.b64 P1, [%0], %1, 0x989680;\n\t" \
            "@P1 bra.uni WAIT_DONE_%=;\n\t" \
            "bra.uni WAIT_LOOP_%=;\n\t" \
            "WAIT_DONE_%=:\n\t}" :: "r"(_mbar), "r"(_parity) : "memory"); \
    } \
} while (0)
#define BULK_G2S(dst_smem, src_gmem, bytes, mbar) \
    asm volatile("cp.async.bulk.shared::cluster.global.mbarrier::complete_tx::bytes [%0], [%1], %2, [%3];" \
        :: "r"((uint32_t)(dst_smem)), "l"(src_gmem), "r"((uint32_t)(bytes)), "r"((uint32_t)(mbar)) : "memory")

// mma.m16n8k16 row.col f32.bf16.bf16.f32 (sm_80+ PTX; no 'a' features)
__device__ __forceinline__ void mma16816(float* c, const uint32_t* a, uint32_t b0, uint32_t b1) {
    asm volatile("mma.sync.aligned.m16n8k16.row.col.f32.bf16.bf16.f32 "
        "{%0,%1,%2,%3}, {%4,%5,%6,%7}, {%8,%9}, {%0,%1,%2,%3};"
        : "+f"(c[0]), "+f"(c[1]), "+f"(c[2]), "+f"(c[3])
        : "r"(a[0]), "r"(a[1]), "r"(a[2]), "r"(a[3]), "r"(b0), "r"(b1));
}

__device__ __forceinline__ float elu_f(float v) { return v > 0.0f ? v : (__expf(v) - 1.0f); }

__device__ __forceinline__ uint32_t pack_hi2(float x, float y, float& lx, float& ly) {
    __nv_bfloat162 h = __floats2bfloat162_rn(x, y);
    lx = x - __bfloat162float(h.x);
    ly = y - __bfloat162float(h.y);
    return *reinterpret_cast<uint32_t*>(&h);
}
__device__ __forceinline__ uint32_t pack2(float x, float y) {
    __nv_bfloat162 h = __floats2bfloat162_rn(x, y);
    return *reinterpret_cast<uint32_t*>(&h);
}

// ---------------- prep: X -> A-fragment order, bf16 hi/lo ----------------
__global__ void prep_x_kernel(const float* __restrict__ X) {
    int gmt = blockIdx.x;
    int t = threadIdx.x;            // 0..319
    int s = t >> 5, lane = t & 31;
    int gid = lane >> 2, tig = lane & 3;
    int r0 = gmt * 16 + gid;
    int c0 = s * 16 + tig * 2;
    float2 v00 = *(const float2*)(X + (size_t)r0 * DD + c0);
    float2 v10 = *(const float2*)(X + (size_t)(r0 + 8) * DD + c0);
    float2 v01 = *(const float2*)(X + (size_t)r0 * DD + c0 + 8);
    float2 v11 = *(const float2*)(X + (size_t)(r0 + 8) * DD + c0 + 8);
    float l00x, l00y, l10x, l10y, l01x, l01y, l11x, l11y;
    uint4 H, L;
    H.x = pack_hi2(v00.x, v00.y, l00x, l00y);
    H.y = pack_hi2(v10.x, v10.y, l10x, l10y);
    H.z = pack_hi2(v01.x, v01.y, l01x, l01y);
    H.w = pack_hi2(v11.x, v11.y, l11x, l11y);
    L.x = pack2(l00x, l00y);
    L.y = pack2(l10x, l10y);
    L.z = pack2(l01x, l01y);
    L.w = pack2(l11x, l11y);
    size_t idx = ((size_t)gmt * KS1 + s) * 32 + lane;
    g_XfragH[idx] = H;
    g_XfragL[idx] = L;
}

// ---------------- prep: W -> B-fragment order + misc, bf16 hi/lo ----------------
__global__ void prep_w_kernel(const float* __restrict__ W1, const float* __restrict__ W2,
                              const float* __restrict__ b1, const float* __restrict__ b2,
                              const float* __restrict__ W3, const float* __restrict__ b3) {
    int f = blockIdx.x;
    unsigned char* blk = g_Wblk + (size_t)f * WBLK;
    uint2* w1h = (uint2*)blk;
    uint2* w1l = (uint2*)(blk + 10240);
    uint2* w2h = (uint2*)(blk + 20480);
    uint2* w2l = (uint2*)(blk + 22528);
    float* misc = (float*)(blk + 24576);

    const float* W1f = W1 + (size_t)f * DD * HH;
    for (int i = threadIdx.x; i < KS1 * 4 * 32; i += blockDim.x) {   // 1280
        int s = i >> 7, nt = (i >> 5) & 3, lane = i & 31;
        int gid = lane >> 2, tig = lane & 3;
        int n = nt * 8 + gid, k0 = s * 16 + tig * 2;
        float w00 = W1f[k0 * HH + n],       w01 = W1f[(k0 + 1) * HH + n];
        float w10 = W1f[(k0 + 8) * HH + n], w11 = W1f[(k0 + 9) * HH + n];
        float l0x, l0y, l1x, l1y;
        uint32_t h0 = pack_hi2(w00, w01, l0x, l0y);
        uint32_t h1 = pack_hi2(w10, w11, l1x, l1y);
        w1h[i] = make_uint2(h0, h1);
        w1l[i] = make_uint2(pack2(l0x, l0y), pack2(l1x, l1y));
    }
    const float* W2f = W2 + (size_t)f * HH * HH;
    for (int i = threadIdx.x; i < 2 * 4 * 32; i += blockDim.x) {     // 256
        int s = i >> 7, nt = (i >> 5) & 3, lane = i & 31;
        int gid = lane >> 2, tig = lane & 3;
        int n = nt * 8 + gid, k0 = s * 16 + tig * 2;
        float w00 = W2f[k0 * HH + n],       w01 = W2f[(k0 + 1) * HH + n];
        float w10 = W2f[(k0 + 8) * HH + n], w11 = W2f[(k0 + 9) * HH + n];
        float l0x, l0y, l1x, l1y;
        uint32_t h0 = pack_hi2(w00, w01, l0x, l0y);
        uint32_t h1 = pack_hi2(w10, w11, l1x, l1y);
        w2h[i] = make_uint2(h0, h1);
        w2l[i] = make_uint2(pack2(l0x, l0y), pack2(l1x, l1y));
    }
    int t = threadIdx.x;
    if (t < HH)            misc[t]      = b1[f * HH + t];
    else if (t < 2 * HH)   misc[t]      = b2[f * HH + (t - HH)];
    else if (t < 3 * HH)   misc[t]      = W3[f * HH + (t - 2 * HH)];
    else if (t == 3 * HH)  misc[96]     = b3[f];
    else if (t < 128)      misc[t]      = 0.0f;
}

// ---------------- main kernel ----------------
#define SM_W   0                         // NSLOT x WBLK ring
#define SM_MB  (NSLOT * WBLK)            // 100352: 4 mbarriers
#define SMEM_DYN (SM_MB + NSLOT * 8)     // 100384

__global__ void __launch_bounds__(NTHR, 1)
mlp_main_kernel(float* __restrict__ out) {
    extern __shared__ unsigned char smem[];
    const uint32_t sb = smem_u32(smem);

    const int tile = blockIdx.x;        // 0..255  (128-row tiles)
    const int f0   = blockIdx.y * NF;   // base network
    const int tid  = threadIdx.x;
    const int wid  = tid >> 5;          // 0..7 -> m-tile within tile
    const int lane = tid & 31;
    const int gid  = lane >> 2, tig = lane & 3;

    if (tid == 0) {
        #pragma unroll
        for (int s = 0; s < NSLOT; s++) MBARRIER_INIT(sb + SM_MB + s * 8, 1);
    }
    __syncthreads();
    if (tid == 0) {
        #pragma unroll
        for (int s = 0; s < NSLOT; s++) {
            MBARRIER_EXPECT_TX(sb + SM_MB + s * 8, (uint32_t)WBLK);
            BULK_G2S(sb + SM_W + s * WBLK,
                     (const void*)(g_Wblk + (size_t)(f0 + s) * WBLK),
                     (uint32_t)WBLK, sb + SM_MB + s * 8);
        }
    }

    // ---- X fragments for this warp's m-tile: live in registers for all 16 f ----
    uint4 xh[KS1], xl[KS1];
    {
        const size_t xbase = ((size_t)(tile * 8 + wid) * KS1) * 32 + lane;
        #pragma unroll
        for (int s = 0; s < KS1; s++) {
            xh[s] = g_XfragH[xbase + (size_t)s * 32];
            xl[s] = g_XfragL[xbase + (size_t)s * 32];
        }
    }

    #pragma unroll 1
    for (int j = 0; j < NF; j++) {
        const int slot = j & (NSLOT - 1);
        MBARRIER_WAIT_PARITY(sb + SM_MB + slot * 8, (j >> 2) & 1);
        const unsigned char* wb = smem + SM_W + slot * WBLK;
        const uint2* W1H = (const uint2*)wb;
        const uint2* W1L = (const uint2*)(wb + 10240);
        const uint2* W2H = (const uint2*)(wb + 20480);
        const uint2* W2L = (const uint2*)(wb + 22528);
        const float* misc = (const float*)(wb + 24576);

        // ---------- layer 1 ----------
        float acc[4][4];
        #pragma unroll
        for (int nt = 0; nt < 4; nt++) {
            float bc0 = misc[nt * 8 + tig * 2];
            float bc1 = misc[nt * 8 + tig * 2 + 1];
            acc[nt][0] = bc0; acc[nt][1] = bc1;
            acc[nt][2] = bc0; acc[nt][3] = bc1;
        }
        #pragma unroll
        for (int s = 0; s < KS1; s++) {
            #pragma unroll
            for (int nt = 0; nt < 4; nt++) {
                uint2 bh = W1H[(s * 4 + nt) * 32 + lane];
                uint2 bl = W1L[(s * 4 + nt) * 32 + lane];
                mma16816(acc[nt], (const uint32_t*)&xh[s], bh.x, bh.y);
                mma16816(acc[nt], (const uint32_t*)&xh[s], bl.x, bl.y);
                mma16816(acc[nt], (const uint32_t*)&xl[s], bh.x, bh.y);
            }
        }

        // ---------- L1 epilogue: elu + split -> layer-2 A frags (registers) ----------
        uint32_t a2H[2][4], a2L[2][4];
        #pragma unroll
        for (int nt = 0; nt < 4; nt++) {
            float v0 = elu_f(acc[nt][0]);
            float v1 = elu_f(acc[nt][1]);
            float v2 = elu_f(acc[nt][2]);
            float v3 = elu_f(acc[nt][3]);
            int s2 = nt >> 1, r = (nt & 1) * 2;
            float lx, ly;
            a2H[s2][r + 0] = pack_hi2(v0, v1, lx, ly);
            a2L[s2][r + 0] = pack2(lx, ly);
            a2H[s2][r + 1] = pack_hi2(v2, v3, lx, ly);
            a2L[s2][r + 1] = pack2(lx, ly);
        }

        // ---------- layer 2 ----------
        float acc2[4][4];
        #pragma unroll
        for (int nt = 0; nt < 4; nt++) {
            float bc0 = misc[32 + nt * 8 + tig * 2];
            float bc1 = misc[32 + nt * 8 + tig * 2 + 1];
            acc2[nt][0] = bc0; acc2[nt][1] = bc1;
            acc2[nt][2] = bc0; acc2[nt][3] = bc1;
        }
        #pragma unroll
        for (int s2 = 0; s2 < 2; s2++) {
            #pragma unroll
            for (int nt = 0; nt < 4; nt++) {
                uint2 bh = W2H[(s2 * 4 + nt) * 32 + lane];
                uint2 bl = W2L[(s2 * 4 + nt) * 32 + lane];
                mma16816(acc2[nt], a2H[s2], bh.x, bh.y);
                mma16816(acc2[nt], a2H[s2], bl.x, bl.y);
                mma16816(acc2[nt], a2L[s2], bh.x, bh.y);
            }
        }

        // ---------- layer 3: dot with W3, reduce over tig quad ----------
        {
            float b3v = misc[96];
            const int f = f0 + j;
            float s0 = 0.0f, s1 = 0.0f;
            #pragma unroll
            for (int nt = 0; nt < 4; nt++) {
                float w0 = misc[64 + nt * 8 + tig * 2];
                float w1 = misc[64 + nt * 8 + tig * 2 + 1];
                s0 += elu_f(acc2[nt][0]) * w0 + elu_f(acc2[nt][1]) * w1;
                s1 += elu_f(acc2[nt][2]) * w0 + elu_f(acc2[nt][3]) * w1;
            }
            s0 += __shfl_xor_sync(0xffffffffu, s0, 1);
            s0 += __shfl_xor_sync(0xffffffffu, s0, 2);
            s1 += __shfl_xor_sync(0xffffffffu, s1, 1);
            s1 += __shfl_xor_sync(0xffffffffu, s1, 2);
            if (tig == 0) {
                int row = tile * ROWS + wid * 16 + gid;
                out[(size_t)row * FF + f]       = s0 + b3v;
                out[(size_t)(row + 8) * FF + f] = s1 + b3v;
            }
        }

        __syncthreads();   // all warps done with this W slot
        if (tid == 0 && j + NSLOT < NF) {
            uint32_t mb = sb + SM_MB + slot * 8;
            MBARRIER_EXPECT_TX(mb, (uint32_t)WBLK);
            BULK_G2S(sb + SM_W + slot * WBLK,
                     (const void*)(g_Wblk + (size_t)(f0 + j + NSLOT) * WBLK),
                     (uint32_t)WBLK, mb);
        }
    }
}

// ---------------- launch ----------------
extern "C" void kernel_launch(void* const* d_in, const int* in_sizes, int n_in,
                              void* d_out, int out_size) {
    const float* X  = (const float*)d_in[0];
    const float* W1 = (const float*)d_in[1];
    const float* b1 = (const float*)d_in[2];
    const float* W2 = (const float*)d_in[3];
    const float* b2 = (const float*)d_in[4];
    const float* W3 = (const float*)d_in[5];
    const float* b3 = (const float*)d_in[6];
    float* out = (float*)d_out;

    static int configured = 0;
    if (!configured) {
        cudaFuncSetAttribute(mlp_main_kernel,
                             cudaFuncAttributeMaxDynamicSharedMemorySize, SMEM_DYN);
        configured = 1;
    }

    prep_x_kernel<<<GMT, 320>>>(X);
    prep_w_kernel<<<FF, 256>>>(W1, W2, b1, b2, W3, b3);
    dim3 grid(NN / ROWS, FF / NF);     // (256, 8)
    mlp_main_kernel<<<grid, NTHR, SMEM_DYN>>>(out);
}

// round 5
// speedup vs baseline: 1.2304x; 1.2304x over previous
#include <cuda_runtime.h>
#include <cuda_fp16.h>
#include <cstdint>

// ---------------- problem constants ----------------
#define NN 32768
#define DD 160     // = 10 k-steps of 16
#define FF 128
#define HH 32      // = 4 n-tiles of 8 = 2 k-steps of 16
#define KS1 10     // layer-1 k-steps
#define ROWS 128   // rows per CTA (8 warps x 1 m-tile)
#define NF 16      // networks per CTA
#define NTHR 256

#define GMT (NN / 16)              // 2048 global m-tiles
#define WBLK 12800                 // per-f weight block bytes (fp16 single W)
#define NSLOT 4                    // W ring depth

// ---------------- device scratch (no allocs) ----------------
__device__ __align__(16) uint4 g_XfragH[(size_t)GMT * KS1 * 32];   // 10.5 MB (fp16 hi)
__device__ __align__(16) uint4 g_XfragL[(size_t)GMT * KS1 * 32];   // 10.5 MB (fp16 lo)
__device__ __align__(16) unsigned char g_Wblk[(size_t)FF * WBLK];  // 1.6 MB
// per-f block: W1H[1280]u2 @0 | W2H[256]u2 @10240 | misc 128 floats @12288

// ---------------- helpers ----------------
__device__ __forceinline__ uint32_t smem_u32(const void* p) {
    uint32_t a;
    asm("{ .reg .u64 t; cvta.to.shared.u64 t, %1; cvt.u32.u64 %0, t; }" : "=r"(a) : "l"(p));
    return a;
}
#define MBARRIER_INIT(addr, cnt) \
    asm volatile("mbarrier.init.shared.b64 [%0], %1;" :: "r"((uint32_t)(addr)), "r"((uint32_t)(cnt)) : "memory")
#define MBARRIER_EXPECT_TX(addr, bytes) \
    asm volatile("mbarrier.arrive.expect_tx.shared.b64 _, [%0], %1;" :: "r"((uint32_t)(addr)), "r"((uint32_t)(bytes)) : "memory")
#define MBARRIER_WAIT_PARITY(mbar_smem_addr, phase_parity) do { \
    uint32_t _mbar = (uint32_t)(mbar_smem_addr); \
    uint32_t _parity = (uint32_t)(phase_parity); \
    uint32_t _done; \
    asm volatile("{\n\t.reg .pred p;\n\t" \
        "mbarrier.try_wait.parity.acquire.cta.shared::cta.b64 p, [%1], %2;\n\t" \
        "selp.b32 %0, 1, 0, p;\n\t}" : "=r"(_done) : "r"(_mbar), "r"(_parity) : "memory"); \
    if (!_done) { \
        asm volatile("{\n\t.reg .pred P1;\n\t" \
            "WAIT_LOOP_%=:\n\t" \
            "mbarrier.try_wait.parity.acquire.cta.shared::cta.b64 P1, [%0], %1, 0x989680;\n\t" \
            "@P1 bra.uni WAIT_DONE_%=;\n\t" \
            "bra.uni WAIT_LOOP_%=;\n\t" \
            "WAIT_DONE_%=:\n\t}" :: "r"(_mbar), "r"(_parity) : "memory"); \
    } \
} while (0)
#define BULK_G2S(dst_smem, src_gmem, bytes, mbar) \
    asm volatile("cp.async.bulk.shared::cluster.global.mbarrier::complete_tx::bytes [%0], [%1], %2, [%3];" \
        :: "r"((uint32_t)(dst_smem)), "l"(src_gmem), "r"((uint32_t)(bytes)), "r"((uint32_t)(mbar)) : "memory")

// mma.m16n8k16 row.col f32.f16.f16.f32 (sm_80+ PTX; no 'a' features)
__device__ __forceinline__ void mma16816(float* c, const uint32_t* a, uint32_t b0, uint32_t b1) {
    asm volatile("mma.sync.aligned.m16n8k16.row.col.f32.f16.f16.f32 "
        "{%0,%1,%2,%3}, {%4,%5,%6,%7}, {%8,%9}, {%0,%1,%2,%3};"
        : "+f"(c[0]), "+f"(c[1]), "+f"(c[2]), "+f"(c[3])
        : "r"(a[0]), "r"(a[1]), "r"(a[2]), "r"(a[3]), "r"(b0), "r"(b1));
}

__device__ __forceinline__ float elu_f(float v) { return v > 0.0f ? v : (__expf(v) - 1.0f); }

// fp16 hi/lo split packers
__device__ __forceinline__ uint32_t packh_hi2(float x, float y, float& lx, float& ly) {
    __half2 h = __floats2half2_rn(x, y);
    lx = x - __half2float(__low2half(h));
    ly = y - __half2float(__high2half(h));
    return *reinterpret_cast<uint32_t*>(&h);
}
__device__ __forceinline__ uint32_t packh2(float x, float y) {
    __half2 h = __floats2half2_rn(x, y);
    return *reinterpret_cast<uint32_t*>(&h);
}

// ---------------- prep: X -> A-fragment order, fp16 hi/lo ----------------
__global__ void prep_x_kernel(const float* __restrict__ X) {
    int gmt = blockIdx.x;
    int t = threadIdx.x;            // 0..319
    int s = t >> 5, lane = t & 31;
    int gid = lane >> 2, tig = lane & 3;
    int r0 = gmt * 16 + gid;
    int c0 = s * 16 + tig * 2;
    float2 v00 = *(const float2*)(X + (size_t)r0 * DD + c0);
    float2 v10 = *(const float2*)(X + (size_t)(r0 + 8) * DD + c0);
    float2 v01 = *(const float2*)(X + (size_t)r0 * DD + c0 + 8);
    float2 v11 = *(const float2*)(X + (size_t)(r0 + 8) * DD + c0 + 8);
    float l00x, l00y, l10x, l10y, l01x, l01y, l11x, l11y;
    uint4 H, L;
    H.x = packh_hi2(v00.x, v00.y, l00x, l00y);
    H.y = packh_hi2(v10.x, v10.y, l10x, l10y);
    H.z = packh_hi2(v01.x, v01.y, l01x, l01y);
    H.w = packh_hi2(v11.x, v11.y, l11x, l11y);
    L.x = packh2(l00x, l00y);
    L.y = packh2(l10x, l10y);
    L.z = packh2(l01x, l01y);
    L.w = packh2(l11x, l11y);
    size_t idx = ((size_t)gmt * KS1 + s) * 32 + lane;
    g_XfragH[idx] = H;
    g_XfragL[idx] = L;
}

// ---------------- prep: W -> B-fragment order (single fp16) + misc ----------------
__global__ void prep_w_kernel(const float* __restrict__ W1, const float* __restrict__ W2,
                              const float* __restrict__ b1, const float* __restrict__ b2,
                              const float* __restrict__ W3, const float* __restrict__ b3) {
    int f = blockIdx.x;
    unsigned char* blk = g_Wblk + (size_t)f * WBLK;
    uint2* w1h = (uint2*)blk;
    uint2* w2h = (uint2*)(blk + 10240);
    float* misc = (float*)(blk + 12288);

    const float* W1f = W1 + (size_t)f * DD * HH;
    for (int i = threadIdx.x; i < KS1 * 4 * 32; i += blockDim.x) {   // 1280
        int s = i >> 7, nt = (i >> 5) & 3, lane = i & 31;
        int gid = lane >> 2, tig = lane & 3;
        int n = nt * 8 + gid, k0 = s * 16 + tig * 2;
        float w00 = W1f[k0 * HH + n],       w01 = W1f[(k0 + 1) * HH + n];
        float w10 = W1f[(k0 + 8) * HH + n], w11 = W1f[(k0 + 9) * HH + n];
        w1h[i] = make_uint2(packh2(w00, w01), packh2(w10, w11));
    }
    const float* W2f = W2 + (size_t)f * HH * HH;
    for (int i = threadIdx.x; i < 2 * 4 * 32; i += blockDim.x) {     // 256
        int s = i >> 7, nt = (i >> 5) & 3, lane = i & 31;
        int gid = lane >> 2, tig = lane & 3;
        int n = nt * 8 + gid, k0 = s * 16 + tig * 2;
        float w00 = W2f[k0 * HH + n],       w01 = W2f[(k0 + 1) * HH + n];
        float w10 = W2f[(k0 + 8) * HH + n], w11 = W2f[(k0 + 9) * HH + n];
        w2h[i] = make_uint2(packh2(w00, w01), packh2(w10, w11));
    }
    int t = threadIdx.x;
    if (t < HH)            misc[t]      = b1[f * HH + t];
    else if (t < 2 * HH)   misc[t]      = b2[f * HH + (t - HH)];
    else if (t < 3 * HH)   misc[t]      = W3[f * HH + (t - 2 * HH)];
    else if (t == 3 * HH)  misc[96]     = b3[f];
    else if (t < 128)      misc[t]      = 0.0f;
}

// ---------------- main kernel ----------------
#define SM_W   0                         // NSLOT x WBLK ring
#define SM_MB  (NSLOT * WBLK)            // 51200
#define SMEM_DYN (SM_MB + NSLOT * 8)     // 51232

__global__ void __launch_bounds__(NTHR, 1)
mlp_main_kernel(float* __restrict__ out) {
    extern __shared__ unsigned char smem[];
    const uint32_t sb = smem_u32(smem);

    const int tile = blockIdx.x;        // 0..255  (128-row tiles)
    const int f0   = blockIdx.y * NF;   // base network
    const int tid  = threadIdx.x;
    const int wid  = tid >> 5;          // 0..7 -> m-tile within tile
    const int lane = tid & 31;
    const int gid  = lane >> 2, tig = lane & 3;

    if (tid == 0) {
        #pragma unroll
        for (int s = 0; s < NSLOT; s++) MBARRIER_INIT(sb + SM_MB + s * 8, 1);
    }
    __syncthreads();
    if (tid == 0) {
        #pragma unroll
        for (int s = 0; s < NSLOT; s++) {
            MBARRIER_EXPECT_TX(sb + SM_MB + s * 8, (uint32_t)WBLK);
            BULK_G2S(sb + SM_W + s * WBLK,
                     (const void*)(g_Wblk + (size_t)(f0 + s) * WBLK),
                     (uint32_t)WBLK, sb + SM_MB + s * 8);
        }
    }

    // ---- X fragments for this warp's m-tile: registers for all 16 f ----
    uint4 xh[KS1], xl[KS1];
    {
        const size_t xbase = ((size_t)(tile * 8 + wid) * KS1) * 32 + lane;
        #pragma unroll
        for (int s = 0; s < KS1; s++) {
            xh[s] = g_XfragH[xbase + (size_t)s * 32];
            xl[s] = g_XfragL[xbase + (size_t)s * 32];
        }
    }

    #pragma unroll 1
    for (int j = 0; j < NF; j++) {
        const int slot = j & (NSLOT - 1);
        MBARRIER_WAIT_PARITY(sb + SM_MB + slot * 8, (j >> 2) & 1);
        const unsigned char* wb = smem + SM_W + slot * WBLK;
        const uint2* W1H = (const uint2*)wb;
        const uint2* W2H = (const uint2*)(wb + 10240);
        const float* misc = (const float*)(wb + 12288);

        // ---------- layer 1: (xh + xl) @ fp16(W1) ----------
        float acc[4][4];
        #pragma unroll
        for (int nt = 0; nt < 4; nt++) {
            float bc0 = misc[nt * 8 + tig * 2];
            float bc1 = misc[nt * 8 + tig * 2 + 1];
            acc[nt][0] = bc0; acc[nt][1] = bc1;
            acc[nt][2] = bc0; acc[nt][3] = bc1;
        }
        #pragma unroll
        for (int s = 0; s < KS1; s++) {
            #pragma unroll
            for (int nt = 0; nt < 4; nt++) {
                uint2 bh = W1H[(s * 4 + nt) * 32 + lane];
                mma16816(acc[nt], (const uint32_t*)&xh[s], bh.x, bh.y);
                mma16816(acc[nt], (const uint32_t*)&xl[s], bh.x, bh.y);
            }
        }

        // ---------- L1 epilogue: elu + fp16 split -> layer-2 A frags ----------
        uint32_t a2H[2][4], a2L[2][4];
        #pragma unroll
        for (int nt = 0; nt < 4; nt++) {
            float v0 = elu_f(acc[nt][0]);
            float v1 = elu_f(acc[nt][1]);
            float v2 = elu_f(acc[nt][2]);
            float v3 = elu_f(acc[nt][3]);
            int s2 = nt >> 1, r = (nt & 1) * 2;
            float lx, ly;
            a2H[s2][r + 0] = packh_hi2(v0, v1, lx, ly);
            a2L[s2][r + 0] = packh2(lx, ly);
            a2H[s2][r + 1] = packh_hi2(v2, v3, lx, ly);
            a2L[s2][r + 1] = packh2(lx, ly);
        }

        // ---------- layer 2: (h1h + h1l) @ fp16(W2) ----------
        float acc2[4][4];
        #pragma unroll
        for (int nt = 0; nt < 4; nt++) {
            float bc0 = misc[32 + nt * 8 + tig * 2];
            float bc1 = misc[32 + nt * 8 + tig * 2 + 1];
            acc2[nt][0] = bc0; acc2[nt][1] = bc1;
            acc2[nt][2] = bc0; acc2[nt][3] = bc1;
        }
        #pragma unroll
        for (int s2 = 0; s2 < 2; s2++) {
            #pragma unroll
            for (int nt = 0; nt < 4; nt++) {
                uint2 bh = W2H[(s2 * 4 + nt) * 32 + lane];
                mma16816(acc2[nt], a2H[s2], bh.x, bh.y);
                mma16816(acc2[nt], a2L[s2], bh.x, bh.y);
            }
        }

        // ---------- layer 3: dot with W3 (fp32), reduce over tig quad ----------
        {
            float b3v = misc[96];
            const int f = f0 + j;
            float s0 = 0.0f, s1 = 0.0f;
            #pragma unroll
            for (int nt = 0; nt < 4; nt++) {
                float w0 = misc[64 + nt * 8 + tig * 2];
                float w1 = misc[64 + nt * 8 + tig * 2 + 1];
                s0 += elu_f(acc2[nt][0]) * w0 + elu_f(acc2[nt][1]) * w1;
                s1 += elu_f(acc2[nt][2]) * w0 + elu_f(acc2[nt][3]) * w1;
            }
            s0 += __shfl_xor_sync(0xffffffffu, s0, 1);
            s0 += __shfl_xor_sync(0xffffffffu, s0, 2);
            s1 += __shfl_xor_sync(0xffffffffu, s1, 1);
            s1 += __shfl_xor_sync(0xffffffffu, s1, 2);
            if (tig == 0) {
                int row = tile * ROWS + wid * 16 + gid;
                out[(size_t)row * FF + f]       = s0 + b3v;
                out[(size_t)(row + 8) * FF + f] = s1 + b3v;
            }
        }

        __syncthreads();   // all warps done with this W slot
        if (tid == 0 && j + NSLOT < NF) {
            uint32_t mb = sb + SM_MB + slot * 8;
            MBARRIER_EXPECT_TX(mb, (uint32_t)WBLK);
            BULK_G2S(sb + SM_W + slot * WBLK,
                     (const void*)(g_Wblk + (size_t)(f0 + j + NSLOT) * WBLK),
                     (uint32_t)WBLK, mb);
        }
    }
}

// ---------------- launch ----------------
extern "C" void kernel_launch(void* const* d_in, const int* in_sizes, int n_in,
                              void* d_out, int out_size) {
    const float* X  = (const float*)d_in[0];
    const float* W1 = (const float*)d_in[1];
    const float* b1 = (const float*)d_in[2];
    const float* W2 = (const float*)d_in[3];
    const float* b2 = (const float*)d_in[4];
    const float* W3 = (const float*)d_in[5];
    const float* b3 = (const float*)d_in[6];
    float* out = (float*)d_out;

    static int configured = 0;
    if (!configured) {
        cudaFuncSetAttribute(mlp_main_kernel,
                             cudaFuncAttributeMaxDynamicSharedMemorySize, SMEM_DYN);
        configured = 1;
    }

    prep_x_kernel<<<GMT, 320>>>(X);
    prep_w_kernel<<<FF, 256>>>(W1, W2, b1, b2, W3, b3);
    dim3 grid(NN / ROWS, FF / NF);     // (256, 8)
    mlp_main_kernel<<<grid, NTHR, SMEM_DYN>>>(out);
}

// round 6
// speedup vs baseline: 1.5648x; 1.2717x over previous
#include <cuda_runtime.h>
#include <cuda_fp16.h>
#include <cstdint>

// ---------------- problem constants ----------------
#define NN 32768
#define DD 160     // = 10 k-steps of 16
#define FF 128
#define HH 32      // = 4 n-tiles of 8 = 2 k-steps of 16
#define KS1 10     // layer-1 k-steps
#define ROWS 128   // rows per CTA (8 warps x 1 m-tile)
#define NF 16      // networks per CTA
#define NTHR 256

#define GMT (NN / 16)              // 2048 global m-tiles
#define WBLK 12800                 // per-f weight block bytes (fp16 single W)
#define NSLOT 4                    // W ring depth

// ---------------- device scratch (no allocs) ----------------
__device__ __align__(16) uint4 g_XfragH[(size_t)GMT * KS1 * 32];   // 10.5 MB (fp16 hi)
__device__ __align__(16) uint4 g_XfragL[(size_t)GMT * KS1 * 32];   // 10.5 MB (fp16 lo)
__device__ __align__(16) unsigned char g_Wblk[(size_t)FF * WBLK];  // 1.6 MB
// per-f block: W1H[1280]u2 @0 | W2H[256]u2 @10240 | misc 128 floats @12288

// ---------------- helpers ----------------
__device__ __forceinline__ uint32_t smem_u32(const void* p) {
    uint32_t a;
    asm("{ .reg .u64 t; cvta.to.shared.u64 t, %1; cvt.u32.u64 %0, t; }" : "=r"(a) : "l"(p));
    return a;
}
#define MBARRIER_INIT(addr, cnt) \
    asm volatile("mbarrier.init.shared.b64 [%0], %1;" :: "r"((uint32_t)(addr)), "r"((uint32_t)(cnt)) : "memory")
#define MBARRIER_EXPECT_TX(addr, bytes) \
    asm volatile("mbarrier.arrive.expect_tx.shared.b64 _, [%0], %1;" :: "r"((uint32_t)(addr)), "r"((uint32_t)(bytes)) : "memory")
#define MBARRIER_WAIT_PARITY(mbar_smem_addr, phase_parity) do { \
    uint32_t _mbar = (uint32_t)(mbar_smem_addr); \
    uint32_t _parity = (uint32_t)(phase_parity); \
    uint32_t _done; \
    asm volatile("{\n\t.reg .pred p;\n\t" \
        "mbarrier.try_wait.parity.acquire.cta.shared::cta.b64 p, [%1], %2;\n\t" \
        "selp.b32 %0, 1, 0, p;\n\t}" : "=r"(_done) : "r"(_mbar), "r"(_parity) : "memory"); \
    if (!_done) { \
        asm volatile("{\n\t.reg .pred P1;\n\t" \
            "WAIT_LOOP_%=:\n\t" \
            "mbarrier.try_wait.parity.acquire.cta.shared::cta.b64 P1, [%0], %1, 0x989680;\n\t" \
            "@P1 bra.uni WAIT_DONE_%=;\n\t" \
            "bra.uni WAIT_LOOP_%=;\n\t" \
            "WAIT_DONE_%=:\n\t}" :: "r"(_mbar), "r"(_parity) : "memory"); \
    } \
} while (0)
#define BULK_G2S(dst_smem, src_gmem, bytes, mbar) \
    asm volatile("cp.async.bulk.shared::cluster.global.mbarrier::complete_tx::bytes [%0], [%1], %2, [%3];" \
        :: "r"((uint32_t)(dst_smem)), "l"(src_gmem), "r"((uint32_t)(bytes)), "r"((uint32_t)(mbar)) : "memory")

// mma.m16n8k16 row.col f32.f16.f16.f32 (sm_80+ PTX; no 'a' features)
__device__ __forceinline__ void mma16816(float* c, const uint32_t* a, uint32_t b0, uint32_t b1) {
    asm volatile("mma.sync.aligned.m16n8k16.row.col.f32.f16.f16.f32 "
        "{%0,%1,%2,%3}, {%4,%5,%6,%7}, {%8,%9}, {%0,%1,%2,%3};"
        : "+f"(c[0]), "+f"(c[1]), "+f"(c[2]), "+f"(c[3])
        : "r"(a[0]), "r"(a[1]), "r"(a[2]), "r"(a[3]), "r"(b0), "r"(b1));
}

__device__ __forceinline__ float elu_f(float v) { return v > 0.0f ? v : (__expf(v) - 1.0f); }

// fp16 hi/lo split packers
__device__ __forceinline__ uint32_t packh_hi2(float x, float y, float& lx, float& ly) {
    __half2 h = __floats2half2_rn(x, y);
    lx = x - __half2float(__low2half(h));
    ly = y - __half2float(__high2half(h));
    return *reinterpret_cast<uint32_t*>(&h);
}
__device__ __forceinline__ uint32_t packh2(float x, float y) {
    __half2 h = __floats2half2_rn(x, y);
    return *reinterpret_cast<uint32_t*>(&h);
}

// ---------------- prep: X -> A-fragment order, fp16 hi/lo ----------------
__global__ void prep_x_kernel(const float* __restrict__ X) {
    int gmt = blockIdx.x;
    int t = threadIdx.x;            // 0..319
    int s = t >> 5, lane = t & 31;
    int gid = lane >> 2, tig = lane & 3;
    int r0 = gmt * 16 + gid;
    int c0 = s * 16 + tig * 2;
    float2 v00 = *(const float2*)(X + (size_t)r0 * DD + c0);
    float2 v10 = *(const float2*)(X + (size_t)(r0 + 8) * DD + c0);
    float2 v01 = *(const float2*)(X + (size_t)r0 * DD + c0 + 8);
    float2 v11 = *(const float2*)(X + (size_t)(r0 + 8) * DD + c0 + 8);
    float l00x, l00y, l10x, l10y, l01x, l01y, l11x, l11y;
    uint4 H, L;
    H.x = packh_hi2(v00.x, v00.y, l00x, l00y);
    H.y = packh_hi2(v10.x, v10.y, l10x, l10y);
    H.z = packh_hi2(v01.x, v01.y, l01x, l01y);
    H.w = packh_hi2(v11.x, v11.y, l11x, l11y);
    L.x = packh2(l00x, l00y);
    L.y = packh2(l10x, l10y);
    L.z = packh2(l01x, l01y);
    L.w = packh2(l11x, l11y);
    size_t idx = ((size_t)gmt * KS1 + s) * 32 + lane;
    g_XfragH[idx] = H;
    g_XfragL[idx] = L;
}

// ---------------- prep: W -> B-fragment order (single fp16) + misc ----------------
__global__ void prep_w_kernel(const float* __restrict__ W1, const float* __restrict__ W2,
                              const float* __restrict__ b1, const float* __restrict__ b2,
                              const float* __restrict__ W3, const float* __restrict__ b3) {
    int f = blockIdx.x;
    unsigned char* blk = g_Wblk + (size_t)f * WBLK;
    uint2* w1h = (uint2*)blk;
    uint2* w2h = (uint2*)(blk + 10240);
    float* misc = (float*)(blk + 12288);

    const float* W1f = W1 + (size_t)f * DD * HH;
    for (int i = threadIdx.x; i < KS1 * 4 * 32; i += blockDim.x) {   // 1280
        int s = i >> 7, nt = (i >> 5) & 3, lane = i & 31;
        int gid = lane >> 2, tig = lane & 3;
        int n = nt * 8 + gid, k0 = s * 16 + tig * 2;
        float w00 = W1f[k0 * HH + n],       w01 = W1f[(k0 + 1) * HH + n];
        float w10 = W1f[(k0 + 8) * HH + n], w11 = W1f[(k0 + 9) * HH + n];
        w1h[i] = make_uint2(packh2(w00, w01), packh2(w10, w11));
    }
    const float* W2f = W2 + (size_t)f * HH * HH;
    for (int i = threadIdx.x; i < 2 * 4 * 32; i += blockDim.x) {     // 256
        int s = i >> 7, nt = (i >> 5) & 3, lane = i & 31;
        int gid = lane >> 2, tig = lane & 3;
        int n = nt * 8 + gid, k0 = s * 16 + tig * 2;
        float w00 = W2f[k0 * HH + n],       w01 = W2f[(k0 + 1) * HH + n];
        float w10 = W2f[(k0 + 8) * HH + n], w11 = W2f[(k0 + 9) * HH + n];
        w2h[i] = make_uint2(packh2(w00, w01), packh2(w10, w11));
    }
    int t = threadIdx.x;
    if (t < HH)            misc[t]      = b1[f * HH + t];
    else if (t < 2 * HH)   misc[t]      = b2[f * HH + (t - HH)];
    else if (t < 3 * HH)   misc[t]      = W3[f * HH + (t - 2 * HH)];
    else if (t == 3 * HH)  misc[96]     = b3[f];
    else if (t < 128)      misc[t]      = 0.0f;
}

// ---------------- main kernel ----------------
// smem: XL stage [8 warps][KS1][32] uint4 = 40960 | W ring 4x12800 = 51200 | mbarriers
#define SM_XL  0
#define SM_W   40960
#define SM_MB  (SM_W + NSLOT * WBLK)        // 92160
#define SMEM_DYN (SM_MB + NSLOT * 8)        // 92192

__global__ void __launch_bounds__(NTHR, 2)
mlp_main_kernel(float* __restrict__ out) {
    extern __shared__ unsigned char smem[];
    const uint32_t sb = smem_u32(smem);

    const int tile = blockIdx.x;        // 0..255  (128-row tiles)
    const int f0   = blockIdx.y * NF;   // base network
    const int tid  = threadIdx.x;
    const int wid  = tid >> 5;          // 0..7 -> m-tile within tile
    const int lane = tid & 31;
    const int gid  = lane >> 2, tig = lane & 3;

    if (tid == 0) {
        #pragma unroll
        for (int s = 0; s < NSLOT; s++) MBARRIER_INIT(sb + SM_MB + s * 8, 1);
    }
    __syncthreads();
    if (tid == 0) {
        #pragma unroll
        for (int s = 0; s < NSLOT; s++) {
            MBARRIER_EXPECT_TX(sb + SM_MB + s * 8, (uint32_t)WBLK);
            BULK_G2S(sb + SM_W + s * WBLK,
                     (const void*)(g_Wblk + (size_t)(f0 + s) * WBLK),
                     (uint32_t)WBLK, sb + SM_MB + s * 8);
        }
    }

    // ---- X hi fragments in registers; lo fragments staged to smem (own slot only,
    //      no sync needed: each thread writes and reads the exact same address) ----
    uint4 xh[KS1];
    uint4* xls = (uint4*)(smem + SM_XL) + (wid * KS1) * 32 + lane;
    {
        const size_t xbase = ((size_t)(tile * 8 + wid) * KS1) * 32 + lane;
        #pragma unroll
        for (int s = 0; s < KS1; s++) {
            xh[s] = g_XfragH[xbase + (size_t)s * 32];
            xls[s * 32] = g_XfragL[xbase + (size_t)s * 32];
        }
    }

    #pragma unroll 1
    for (int j = 0; j < NF; j++) {
        const int slot = j & (NSLOT - 1);
        MBARRIER_WAIT_PARITY(sb + SM_MB + slot * 8, (j >> 2) & 1);
        const unsigned char* wb = smem + SM_W + slot * WBLK;
        const uint2* W1H = (const uint2*)wb;
        const uint2* W2H = (const uint2*)(wb + 10240);
        const float* misc = (const float*)(wb + 12288);

        // ---------- layer 1: (xh + xl) @ fp16(W1) ----------
        float acc[4][4];
        #pragma unroll
        for (int nt = 0; nt < 4; nt++) {
            float bc0 = misc[nt * 8 + tig * 2];
            float bc1 = misc[nt * 8 + tig * 2 + 1];
            acc[nt][0] = bc0; acc[nt][1] = bc1;
            acc[nt][2] = bc0; acc[nt][3] = bc1;
        }
        #pragma unroll
        for (int s = 0; s < KS1; s++) {
            uint4 xlv = xls[s * 32];
            uint2 bh0 = W1H[(s * 4 + 0) * 32 + lane];
            uint2 bh1 = W1H[(s * 4 + 1) * 32 + lane];
            uint2 bh2 = W1H[(s * 4 + 2) * 32 + lane];
            uint2 bh3 = W1H[(s * 4 + 3) * 32 + lane];
            // pass-outer issue order: 4 independent accumulator chains back-to-back
            mma16816(acc[0], (const uint32_t*)&xh[s], bh0.x, bh0.y);
            mma16816(acc[1], (const uint32_t*)&xh[s], bh1.x, bh1.y);
            mma16816(acc[2], (const uint32_t*)&xh[s], bh2.x, bh2.y);
            mma16816(acc[3], (const uint32_t*)&xh[s], bh3.x, bh3.y);
            mma16816(acc[0], (const uint32_t*)&xlv, bh0.x, bh0.y);
            mma16816(acc[1], (const uint32_t*)&xlv, bh1.x, bh1.y);
            mma16816(acc[2], (const uint32_t*)&xlv, bh2.x, bh2.y);
            mma16816(acc[3], (const uint32_t*)&xlv, bh3.x, bh3.y);
        }

        // ---------- L1 epilogue: elu + fp16 split -> layer-2 A frags ----------
        uint32_t a2H[2][4], a2L[2][4];
        #pragma unroll
        for (int nt = 0; nt < 4; nt++) {
            float v0 = elu_f(acc[nt][0]);
            float v1 = elu_f(acc[nt][1]);
            float v2 = elu_f(acc[nt][2]);
            float v3 = elu_f(acc[nt][3]);
            int s2 = nt >> 1, r = (nt & 1) * 2;
            float lx, ly;
            a2H[s2][r + 0] = packh_hi2(v0, v1, lx, ly);
            a2L[s2][r + 0] = packh2(lx, ly);
            a2H[s2][r + 1] = packh_hi2(v2, v3, lx, ly);
            a2L[s2][r + 1] = packh2(lx, ly);
        }

        // ---------- layer 2: (h1h + h1l) @ fp16(W2) ----------
        float acc2[4][4];
        #pragma unroll
        for (int nt = 0; nt < 4; nt++) {
            float bc0 = misc[32 + nt * 8 + tig * 2];
            float bc1 = misc[32 + nt * 8 + tig * 2 + 1];
            acc2[nt][0] = bc0; acc2[nt][1] = bc1;
            acc2[nt][2] = bc0; acc2[nt][3] = bc1;
        }
        #pragma unroll
        for (int s2 = 0; s2 < 2; s2++) {
            uint2 bh0 = W2H[(s2 * 4 + 0) * 32 + lane];
            uint2 bh1 = W2H[(s2 * 4 + 1) * 32 + lane];
            uint2 bh2 = W2H[(s2 * 4 + 2) * 32 + lane];
            uint2 bh3 = W2H[(s2 * 4 + 3) * 32 + lane];
            mma16816(acc2[0], a2H[s2], bh0.x, bh0.y);
            mma16816(acc2[1], a2H[s2], bh1.x, bh1.y);
            mma16816(acc2[2], a2H[s2], bh2.x, bh2.y);
            mma16816(acc2[3], a2H[s2], bh3.x, bh3.y);
            mma16816(acc2[0], a2L[s2], bh0.x, bh0.y);
            mma16816(acc2[1], a2L[s2], bh1.x, bh1.y);
            mma16816(acc2[2], a2L[s2], bh2.x, bh2.y);
            mma16816(acc2[3], a2L[s2], bh3.x, bh3.y);
        }

        // ---------- layer 3: dot with W3 (fp32), reduce over tig quad ----------
        {
            float b3v = misc[96];
            const int f = f0 + j;
            float s0 = 0.0f, s1 = 0.0f;
            #pragma unroll
            for (int nt = 0; nt < 4; nt++) {
                float w0 = misc[64 + nt * 8 + tig * 2];
                float w1 = misc[64 + nt * 8 + tig * 2 + 1];
                s0 += elu_f(acc2[nt][0]) * w0 + elu_f(acc2[nt][1]) * w1;
                s1 += elu_f(acc2[nt][2]) * w0 + elu_f(acc2[nt][3]) * w1;
            }
            s0 += __shfl_xor_sync(0xffffffffu, s0, 1);
            s0 += __shfl_xor_sync(0xffffffffu, s0, 2);
            s1 += __shfl_xor_sync(0xffffffffu, s1, 1);
            s1 += __shfl_xor_sync(0xffffffffu, s1, 2);
            if (tig == 0) {
                int row = tile * ROWS + wid * 16 + gid;
                out[(size_t)row * FF + f]       = s0 + b3v;
                out[(size_t)(row + 8) * FF + f] = s1 + b3v;
            }
        }

        __syncthreads();   // all warps done with this W slot
        if (tid == 0 && j + NSLOT < NF) {
            uint32_t mb = sb + SM_MB + slot * 8;
            MBARRIER_EXPECT_TX(mb, (uint32_t)WBLK);
            BULK_G2S(sb + SM_W + slot * WBLK,
                     (const void*)(g_Wblk + (size_t)(f0 + j + NSLOT) * WBLK),
                     (uint32_t)WBLK, mb);
        }
    }
}

// ---------------- launch ----------------
extern "C" void kernel_launch(void* const* d_in, const int* in_sizes, int n_in,
                              void* d_out, int out_size) {
    const float* X  = (const float*)d_in[0];
    const float* W1 = (const float*)d_in[1];
    const float* b1 = (const float*)d_in[2];
    const float* W2 = (const float*)d_in[3];
    const float* b2 = (const float*)d_in[4];
    const float* W3 = (const float*)d_in[5];
    const float* b3 = (const float*)d_in[6];
    float* out = (float*)d_out;

    static int configured = 0;
    if (!configured) {
        cudaFuncSetAttribute(mlp_main_kernel,
                             cudaFuncAttributeMaxDynamicSharedMemorySize, SMEM_DYN);
        configured = 1;
    }

    prep_x_kernel<<<GMT, 320>>>(X);
    prep_w_kernel<<<FF, 256>>>(W1, W2, b1, b2, W3, b3);
    dim3 grid(NN / ROWS, FF / NF);     // (256, 8)
    mlp_main_kernel<<<grid, NTHR, SMEM_DYN>>>(out);
}

// round 7
// speedup vs baseline: 2.7626x; 1.7655x over previous
#include <cuda_runtime.h>
#include <cuda_fp16.h>
#include <cstdint>

// ---------------- problem constants ----------------
#define NN 32768
#define DD 160     // = 10 k-steps of 16
#define FF 128
#define HH 32      // = 4 n-tiles of 8 = 2 k-steps of 16
#define KS1 10     // layer-1 k-steps
#define ROWS 128   // rows per CTA (8 warps x 1 m-tile)
#define NF 16      // networks per CTA
#define NTHR 256

#define GMT (NN / 16)              // 2048 global m-tiles
#define WBLK 12800                 // per-f weight block bytes (fp16 single W)
#define NSLOT 4                    // W ring depth

// ---------------- device scratch (no allocs) ----------------
__device__ __align__(16) uint4 g_XfragH[(size_t)GMT * KS1 * 32];   // 10.5 MB (fp16)
__device__ __align__(16) unsigned char g_Wblk[(size_t)FF * WBLK];  // 1.6 MB
// per-f block: W1H[1280]u2 @0 | W2H[256]u2 @10240 | misc 128 floats @12288

// ---------------- helpers ----------------
__device__ __forceinline__ uint32_t smem_u32(const void* p) {
    uint32_t a;
    asm("{ .reg .u64 t; cvta.to.shared.u64 t, %1; cvt.u32.u64 %0, t; }" : "=r"(a) : "l"(p));
    return a;
}
#define MBARRIER_INIT(addr, cnt) \
    asm volatile("mbarrier.init.shared.b64 [%0], %1;" :: "r"((uint32_t)(addr)), "r"((uint32_t)(cnt)) : "memory")
#define MBARRIER_EXPECT_TX(addr, bytes) \
    asm volatile("mbarrier.arrive.expect_tx.shared.b64 _, [%0], %1;" :: "r"((uint32_t)(addr)), "r"((uint32_t)(bytes)) : "memory")
#define MBARRIER_WAIT_PARITY(mbar_smem_addr, phase_parity) do { \
    uint32_t _mbar = (uint32_t)(mbar_smem_addr); \
    uint32_t _parity = (uint32_t)(phase_parity); \
    uint32_t _done; \
    asm volatile("{\n\t.reg .pred p;\n\t" \
        "mbarrier.try_wait.parity.acquire.cta.shared::cta.b64 p, [%1], %2;\n\t" \
        "selp.b32 %0, 1, 0, p;\n\t}" : "=r"(_done) : "r"(_mbar), "r"(_parity) : "memory"); \
    if (!_done) { \
        asm volatile("{\n\t.reg .pred P1;\n\t" \
            "WAIT_LOOP_%=:\n\t" \
            "mbarrier.try_wait.parity.acquire.cta.shared::cta.b64 P1, [%0], %1, 0x989680;\n\t" \
            "@P1 bra.uni WAIT_DONE_%=;\n\t" \
            "bra.uni WAIT_LOOP_%=;\n\t" \
            "WAIT_DONE_%=:\n\t}" :: "r"(_mbar), "r"(_parity) : "memory"); \
    } \
} while (0)
#define BULK_G2S(dst_smem, src_gmem, bytes, mbar) \
    asm volatile("cp.async.bulk.shared::cluster.global.mbarrier::complete_tx::bytes [%0], [%1], %2, [%3];" \
        :: "r"((uint32_t)(dst_smem)), "l"(src_gmem), "r"((uint32_t)(bytes)), "r"((uint32_t)(mbar)) : "memory")

// mma.m16n8k16 row.col f32.f16.f16.f32 (sm_80+ PTX; no 'a' features)
__device__ __forceinline__ void mma16816(float* c, const uint32_t* a, uint32_t b0, uint32_t b1) {
    asm volatile("mma.sync.aligned.m16n8k16.row.col.f32.f16.f16.f32 "
        "{%0,%1,%2,%3}, {%4,%5,%6,%7}, {%8,%9}, {%0,%1,%2,%3};"
        : "+f"(c[0]), "+f"(c[1]), "+f"(c[2]), "+f"(c[3])
        : "r"(a[0]), "r"(a[1]), "r"(a[2]), "r"(a[3]), "r"(b0), "r"(b1));
}

__device__ __forceinline__ float elu_f(float v) { return v > 0.0f ? v : (__expf(v) - 1.0f); }

__device__ __forceinline__ uint32_t packh2(float x, float y) {
    __half2 h = __floats2half2_rn(x, y);
    return *reinterpret_cast<uint32_t*>(&h);
}

// ---------------- prep: X -> A-fragment order, fp16 ----------------
__global__ void prep_x_kernel(const float* __restrict__ X) {
    int gmt = blockIdx.x;
    int t = threadIdx.x;            // 0..319
    int s = t >> 5, lane = t & 31;
    int gid = lane >> 2, tig = lane & 3;
    int r0 = gmt * 16 + gid;
    int c0 = s * 16 + tig * 2;
    float2 v00 = *(const float2*)(X + (size_t)r0 * DD + c0);
    float2 v10 = *(const float2*)(X + (size_t)(r0 + 8) * DD + c0);
    float2 v01 = *(const float2*)(X + (size_t)r0 * DD + c0 + 8);
    float2 v11 = *(const float2*)(X + (size_t)(r0 + 8) * DD + c0 + 8);
    uint4 H;
    H.x = packh2(v00.x, v00.y);
    H.y = packh2(v10.x, v10.y);
    H.z = packh2(v01.x, v01.y);
    H.w = packh2(v11.x, v11.y);
    g_XfragH[((size_t)gmt * KS1 + s) * 32 + lane] = H;
}

// ---------------- prep: W -> B-fragment order (fp16) + misc ----------------
__global__ void prep_w_kernel(const float* __restrict__ W1, const float* __restrict__ W2,
                              const float* __restrict__ b1, const float* __restrict__ b2,
                              const float* __restrict__ W3, const float* __restrict__ b3) {
    int f = blockIdx.x;
    unsigned char* blk = g_Wblk + (size_t)f * WBLK;
    uint2* w1h = (uint2*)blk;
    uint2* w2h = (uint2*)(blk + 10240);
    float* misc = (float*)(blk + 12288);

    const float* W1f = W1 + (size_t)f * DD * HH;
    for (int i = threadIdx.x; i < KS1 * 4 * 32; i += blockDim.x) {   // 1280
        int s = i >> 7, nt = (i >> 5) & 3, lane = i & 31;
        int gid = lane >> 2, tig = lane & 3;
        int n = nt * 8 + gid, k0 = s * 16 + tig * 2;
        float w00 = W1f[k0 * HH + n],       w01 = W1f[(k0 + 1) * HH + n];
        float w10 = W1f[(k0 + 8) * HH + n], w11 = W1f[(k0 + 9) * HH + n];
        w1h[i] = make_uint2(packh2(w00, w01), packh2(w10, w11));
    }
    const float* W2f = W2 + (size_t)f * HH * HH;
    for (int i = threadIdx.x; i < 2 * 4 * 32; i += blockDim.x) {     // 256
        int s = i >> 7, nt = (i >> 5) & 3, lane = i & 31;
        int gid = lane >> 2, tig = lane & 3;
        int n = nt * 8 + gid, k0 = s * 16 + tig * 2;
        float w00 = W2f[k0 * HH + n],       w01 = W2f[(k0 + 1) * HH + n];
        float w10 = W2f[(k0 + 8) * HH + n], w11 = W2f[(k0 + 9) * HH + n];
        w2h[i] = make_uint2(packh2(w00, w01), packh2(w10, w11));
    }
    int t = threadIdx.x;
    if (t < HH)            misc[t]      = b1[f * HH + t];
    else if (t < 2 * HH)   misc[t]      = b2[f * HH + (t - HH)];
    else if (t < 3 * HH)   misc[t]      = W3[f * HH + (t - 2 * HH)];
    else if (t == 3 * HH)  misc[96]     = b3[f];
    else if (t < 128)      misc[t]      = 0.0f;
}

// ---------------- main kernel ----------------
#define SM_W   0                            // NSLOT x WBLK ring
#define SM_MB  (SM_W + NSLOT * WBLK)        // 51200
#define SMEM_DYN (SM_MB + NSLOT * 8)        // 51232

__global__ void __launch_bounds__(NTHR, 3)
mlp_main_kernel(float* __restrict__ out) {
    extern __shared__ unsigned char smem[];
    const uint32_t sb = smem_u32(smem);

    const int tile = blockIdx.x;        // 0..255  (128-row tiles)
    const int f0   = blockIdx.y * NF;   // base network
    const int tid  = threadIdx.x;
    const int wid  = tid >> 5;          // 0..7 -> m-tile within tile
    const int lane = tid & 31;
    const int gid  = lane >> 2, tig = lane & 3;

    if (tid == 0) {
        #pragma unroll
        for (int s = 0; s < NSLOT; s++) MBARRIER_INIT(sb + SM_MB + s * 8, 1);
    }
    __syncthreads();
    if (tid == 0) {
        #pragma unroll
        for (int s = 0; s < NSLOT; s++) {
            MBARRIER_EXPECT_TX(sb + SM_MB + s * 8, (uint32_t)WBLK);
            BULK_G2S(sb + SM_W + s * WBLK,
                     (const void*)(g_Wblk + (size_t)(f0 + s) * WBLK),
                     (uint32_t)WBLK, sb + SM_MB + s * 8);
        }
    }

    // ---- X fragments for this warp's m-tile: registers for all 16 f ----
    uint4 xh[KS1];
    {
        const size_t xbase = ((size_t)(tile * 8 + wid) * KS1) * 32 + lane;
        #pragma unroll
        for (int s = 0; s < KS1; s++)
            xh[s] = g_XfragH[xbase + (size_t)s * 32];
    }

    #pragma unroll 1
    for (int j = 0; j < NF; j++) {
        const int slot = j & (NSLOT - 1);
        MBARRIER_WAIT_PARITY(sb + SM_MB + slot * 8, (j >> 2) & 1);
        const unsigned char* wb = smem + SM_W + slot * WBLK;
        const uint2* W1H = (const uint2*)wb;
        const uint2* W2H = (const uint2*)(wb + 10240);
        const float* misc = (const float*)(wb + 12288);

        // ---------- layer 1: fp16(x) @ fp16(W1) ----------
        float acc[4][4];
        #pragma unroll
        for (int nt = 0; nt < 4; nt++) {
            float bc0 = misc[nt * 8 + tig * 2];
            float bc1 = misc[nt * 8 + tig * 2 + 1];
            acc[nt][0] = bc0; acc[nt][1] = bc1;
            acc[nt][2] = bc0; acc[nt][3] = bc1;
        }
        #pragma unroll
        for (int s = 0; s < KS1; s++) {
            uint2 bh0 = W1H[(s * 4 + 0) * 32 + lane];
            uint2 bh1 = W1H[(s * 4 + 1) * 32 + lane];
            uint2 bh2 = W1H[(s * 4 + 2) * 32 + lane];
            uint2 bh3 = W1H[(s * 4 + 3) * 32 + lane];
            mma16816(acc[0], (const uint32_t*)&xh[s], bh0.x, bh0.y);
            mma16816(acc[1], (const uint32_t*)&xh[s], bh1.x, bh1.y);
            mma16816(acc[2], (const uint32_t*)&xh[s], bh2.x, bh2.y);
            mma16816(acc[3], (const uint32_t*)&xh[s], bh3.x, bh3.y);
        }

        // ---------- L1 epilogue: elu + fp16 -> layer-2 A frags ----------
        uint32_t a2H[2][4];
        #pragma unroll
        for (int nt = 0; nt < 4; nt++) {
            float v0 = elu_f(acc[nt][0]);
            float v1 = elu_f(acc[nt][1]);
            float v2 = elu_f(acc[nt][2]);
            float v3 = elu_f(acc[nt][3]);
            int s2 = nt >> 1, r = (nt & 1) * 2;
            a2H[s2][r + 0] = packh2(v0, v1);
            a2H[s2][r + 1] = packh2(v2, v3);
        }

        // ---------- layer 2: fp16(h1) @ fp16(W2) ----------
        float acc2[4][4];
        #pragma unroll
        for (int nt = 0; nt < 4; nt++) {
            float bc0 = misc[32 + nt * 8 + tig * 2];
            float bc1 = misc[32 + nt * 8 + tig * 2 + 1];
            acc2[nt][0] = bc0; acc2[nt][1] = bc1;
            acc2[nt][2] = bc0; acc2[nt][3] = bc1;
        }
        #pragma unroll
        for (int s2 = 0; s2 < 2; s2++) {
            uint2 bh0 = W2H[(s2 * 4 + 0) * 32 + lane];
            uint2 bh1 = W2H[(s2 * 4 + 1) * 32 + lane];
            uint2 bh2 = W2H[(s2 * 4 + 2) * 32 + lane];
            uint2 bh3 = W2H[(s2 * 4 + 3) * 32 + lane];
            mma16816(acc2[0], a2H[s2], bh0.x, bh0.y);
            mma16816(acc2[1], a2H[s2], bh1.x, bh1.y);
            mma16816(acc2[2], a2H[s2], bh2.x, bh2.y);
            mma16816(acc2[3], a2H[s2], bh3.x, bh3.y);
        }

        // ---------- layer 3: dot with W3 (fp32), reduce over tig quad ----------
        {
            float b3v = misc[96];
            const int f = f0 + j;
            float s0 = 0.0f, s1 = 0.0f;
            #pragma unroll
            for (int nt = 0; nt < 4; nt++) {
                float w0 = misc[64 + nt * 8 + tig * 2];
                float w1 = misc[64 + nt * 8 + tig * 2 + 1];
                s0 += elu_f(acc2[nt][0]) * w0 + elu_f(acc2[nt][1]) * w1;
                s1 += elu_f(acc2[nt][2]) * w0 + elu_f(acc2[nt][3]) * w1;
            }
            s0 += __shfl_xor_sync(0xffffffffu, s0, 1);
            s0 += __shfl_xor_sync(0xffffffffu, s0, 2);
            s1 += __shfl_xor_sync(0xffffffffu, s1, 1);
            s1 += __shfl_xor_sync(0xffffffffu, s1, 2);
            if (tig == 0) {
                int row = tile * ROWS + wid * 16 + gid;
                out[(size_t)row * FF + f]       = s0 + b3v;
                out[(size_t)(row + 8) * FF + f] = s1 + b3v;
            }
        }

        __syncthreads();   // all warps done with this W slot
        if (tid == 0 && j + NSLOT < NF) {
            uint32_t mb = sb + SM_MB + slot * 8;
            MBARRIER_EXPECT_TX(mb, (uint32_t)WBLK);
            BULK_G2S(sb + SM_W + slot * WBLK,
                     (const void*)(g_Wblk + (size_t)(f0 + j + NSLOT) * WBLK),
                     (uint32_t)WBLK, mb);
        }
    }
}

// ---------------- launch ----------------
extern "C" void kernel_launch(void* const* d_in, const int* in_sizes, int n_in,
                              void* d_out, int out_size) {
    const float* X  = (const float*)d_in[0];
    const float* W1 = (const float*)d_in[1];
    const float* b1 = (const float*)d_in[2];
    const float* W2 = (const float*)d_in[3];
    const float* b2 = (const float*)d_in[4];
    const float* W3 = (const float*)d_in[5];
    const float* b3 = (const float*)d_in[6];
    float* out = (float*)d_out;

    static int configured = 0;
    if (!configured) {
        cudaFuncSetAttribute(mlp_main_kernel,
                             cudaFuncAttributeMaxDynamicSharedMemorySize, SMEM_DYN);
        configured = 1;
    }

    prep_x_kernel<<<GMT, 320>>>(X);
    prep_w_kernel<<<FF, 256>>>(W1, W2, b1, b2, W3, b3);
    dim3 grid(NN / ROWS, FF / NF);     // (256, 8)
    mlp_main_kernel<<<grid, NTHR, SMEM_DYN>>>(out);
}